// round 1
// baseline (speedup 1.0000x reference)
#include <cuda_runtime.h>
#include <math.h>

// ---------------- problem constants ----------------
#define BATCH 2048
#define NC    4
#define NRIS  100
#define DIN   303
#define D1    1024
#define D2    1024
#define D3    512
#define DOUT  264
// 1/THRESH_W = 1 / (10^(-12) / 1000) = 1e15
#define INV_THRESH 1.0e15f

// ---------------- scratch (static device allocations; no cudaMalloc) --------
__device__ float g_h1[BATCH * D1];
__device__ float g_h2[BATCH * D2];
__device__ float g_h3[BATCH * D3];
__device__ float g_t1[BATCH * DOUT];
__device__ float g_thetaN[BATCH * 2 * NRIS];

// ---------------- fp32 tiled GEMM + bias (+ optional ReLU) ------------------
// A: [M,K] row-major, W: [K,N] row-major, C: [M,N]
template <int BM, int BN, int BK, int TM, int TN, bool RELU>
__global__ __launch_bounds__(256) void sgemm_bias(
    const float* __restrict__ A, const float* __restrict__ W,
    const float* __restrict__ bias, float* __restrict__ Cmat,
    int M, int N, int K)
{
    __shared__ float As[BK][BM + 4];   // +4 pad to break store conflicts
    __shared__ float Bs[BK][BN];

    const int tid = threadIdx.x;
    const int bm  = blockIdx.y * BM;
    const int bn  = blockIdx.x * BN;
    const int tx  = tid % (BN / TN);   // 16
    const int ty  = tid / (BN / TN);   // 16

    float acc[TM][TN];
#pragma unroll
    for (int i = 0; i < TM; i++)
#pragma unroll
        for (int j = 0; j < TN; j++) acc[i][j] = 0.f;

    for (int k0 = 0; k0 < K; k0 += BK) {
        // load A tile (transposed into As[k][m])
#pragma unroll
        for (int i = 0; i < (BM * BK) / 256; i++) {
            int idx = tid + i * 256;
            int m  = idx / BK;
            int kk = idx % BK;
            int gm = bm + m, gk = k0 + kk;
            float v = 0.f;
            if (gm < M && gk < K) v = A[(size_t)gm * K + gk];
            As[kk][m] = v;
        }
        // load W tile
#pragma unroll
        for (int i = 0; i < (BK * BN) / 256; i++) {
            int idx = tid + i * 256;
            int kk = idx / BN;
            int n  = idx % BN;
            int gk = k0 + kk, gn = bn + n;
            float v = 0.f;
            if (gk < K && gn < N) v = W[(size_t)gk * N + gn];
            Bs[kk][n] = v;
        }
        __syncthreads();

#pragma unroll
        for (int kk = 0; kk < BK; kk++) {
            float a[TM], bb[TN];
#pragma unroll
            for (int i = 0; i < TM; i++) a[i] = As[kk][ty * TM + i];
#pragma unroll
            for (int j = 0; j < TN; j++) bb[j] = Bs[kk][tx * TN + j];
#pragma unroll
            for (int i = 0; i < TM; i++)
#pragma unroll
                for (int j = 0; j < TN; j++)
                    acc[i][j] = fmaf(a[i], bb[j], acc[i][j]);
        }
        __syncthreads();
    }

#pragma unroll
    for (int i = 0; i < TM; i++) {
        int gm = bm + ty * TM + i;
        if (gm >= M) continue;
#pragma unroll
        for (int j = 0; j < TN; j++) {
            int gn = bn + tx * TN + j;
            if (gn >= N) continue;
            float v = acc[i][j] + bias[gn];
            if (RELU) v = fmaxf(v, 0.f);
            Cmat[(size_t)gm * N + gn] = v;
        }
    }
}

// ---------------- postprocess: unit-modulus theta + precoder normalization --
// One block (128 threads) per sample.
__global__ __launch_bounds__(128) void postproc_kernel(
    const float* __restrict__ t1, float* __restrict__ thetaN,
    float* __restrict__ out)
{
    const int b   = blockIdx.x;
    const int tid = threadIdx.x;
    const float* row  = t1  + (size_t)b * DOUT;
    float*       orow = out + (size_t)b * DOUT;

    __shared__ float s[2];

    // theta / |theta|  (elementwise)
    if (tid < NRIS) {
        float re = row[tid];
        float im = row[NRIS + tid];
        float inv = rsqrtf(re * re + im * im);
        thetaN[(size_t)b * 200 + tid]        = re * inv;
        thetaN[(size_t)b * 200 + 100 + tid]  = im * inv;
    }

    // F1 (warp 0) and F2 (warp 1) norms: sqrt(2 / sum|F|^2)
    int w = tid >> 5, l = tid & 31;
    if (w < 2) {
        int base = 200 + 32 * w;   // 200 for F1, 232 for F2
        float v = 0.f;
        if (l < 16) {
            float re = row[base + l];
            float im = row[base + 16 + l];
            v = re * re + im * im;
        }
#pragma unroll
        for (int o = 8; o; o >>= 1) v += __shfl_down_sync(0xffffffffu, v, o);
        if (l == 0) s[w] = sqrtf(2.0f / v);
    }
    __syncthreads();

    // write scaled F parts: cols 200..231 (F1 re/im), 232..263 (F2 re/im)
    if (tid < 64) {
        int col  = 200 + tid;
        float sc = (tid < 32) ? s[0] : s[1];
        orow[col] = row[col] * sc;
    }
}

// ---------------- quadratic form + rescale: HBM-bound streaming -------------
// One block (512 threads) per sample; 4 groups of 128 threads, one per
// constraint matrix c. CCC_c = Re(theta^H T_c theta) / THRESH_W.
// Then scale = rsqrt(max(max_c CCC, 1)) and write theta_hat into out[:,0:200].
__global__ __launch_bounds__(512) void quad_kernel(
    const float* __restrict__ Tr, const float* __restrict__ Ti,
    const float* __restrict__ thetaN, float* __restrict__ out)
{
    const int b   = blockIdx.x;
    const int tid = threadIdx.x;

    __shared__ float sth[200];      // [a(0..99), b(100..199)]
    __shared__ float partial[16];   // per-warp partials
    __shared__ float sccc[4];
    __shared__ float sscale;

    if (tid < 200) sth[tid] = thetaN[(size_t)b * 200 + tid];
    __syncthreads();

    const int c  = tid >> 7;    // 0..3
    const int lt = tid & 127;

    const float4* TrV = (const float4*)(Tr + ((size_t)b * NC + c) * 10000);
    const float4* TiV = (const float4*)(Ti + ((size_t)b * NC + c) * 10000);

    float acc = 0.f;
    // 10000 floats = 2500 float4 per matrix; each row (100 floats) = 25 float4
    for (int i = lt; i < 2500; i += 128) {
        int n  = i / 25;
        int m0 = (i - n * 25) * 4;
        float4 tr = TrV[i];
        float4 ti = TiV[i];
        float an = sth[n], bn = sth[100 + n];
        float am, bm;
        am = sth[m0 + 0]; bm = sth[100 + m0 + 0];
        acc += tr.x * (an * am + bn * bm) - ti.x * (an * bm - bn * am);
        am = sth[m0 + 1]; bm = sth[100 + m0 + 1];
        acc += tr.y * (an * am + bn * bm) - ti.y * (an * bm - bn * am);
        am = sth[m0 + 2]; bm = sth[100 + m0 + 2];
        acc += tr.z * (an * am + bn * bm) - ti.z * (an * bm - bn * am);
        am = sth[m0 + 3]; bm = sth[100 + m0 + 3];
        acc += tr.w * (an * am + bn * bm) - ti.w * (an * bm - bn * am);
    }

#pragma unroll
    for (int o = 16; o; o >>= 1) acc += __shfl_down_sync(0xffffffffu, acc, o);
    if ((tid & 31) == 0) partial[tid >> 5] = acc;
    __syncthreads();

    if (tid < 4) {
        float s = partial[tid * 4] + partial[tid * 4 + 1] +
                  partial[tid * 4 + 2] + partial[tid * 4 + 3];
        sccc[tid] = s * INV_THRESH;
    }
    __syncthreads();
    if (tid == 0) {
        float mx = fmaxf(fmaxf(sccc[0], sccc[1]), fmaxf(sccc[2], sccc[3]));
        sscale = rsqrtf(fmaxf(mx, 1.0f));
    }
    __syncthreads();

    if (tid < 200) out[(size_t)b * DOUT + tid] = sth[tid] * sscale;
}

// ---------------- launch ----------------------------------------------------
extern "C" void kernel_launch(void* const* d_in, const int* in_sizes, int n_in,
                              void* d_out, int out_size)
{
    const float* X  = (const float*)d_in[0];
    const float* Tr = (const float*)d_in[1];
    const float* Ti = (const float*)d_in[2];
    const float* W1 = (const float*)d_in[3];
    const float* b1 = (const float*)d_in[4];
    const float* W2 = (const float*)d_in[5];
    const float* b2 = (const float*)d_in[6];
    const float* W3 = (const float*)d_in[7];
    const float* b3 = (const float*)d_in[8];
    const float* W4 = (const float*)d_in[9];
    const float* b4 = (const float*)d_in[10];
    float* out = (float*)d_out;

    float *h1, *h2, *h3, *t1, *thN;
    cudaGetSymbolAddress((void**)&h1,  g_h1);
    cudaGetSymbolAddress((void**)&h2,  g_h2);
    cudaGetSymbolAddress((void**)&h3,  g_h3);
    cudaGetSymbolAddress((void**)&t1,  g_t1);
    cudaGetSymbolAddress((void**)&thN, g_thetaN);

    dim3 blk(256);
    sgemm_bias<128, 128, 8, 8, 8, true ><<<dim3(D1 / 128, BATCH / 128), blk>>>(
        X, W1, b1, h1, BATCH, D1, DIN);
    sgemm_bias<128, 128, 8, 8, 8, true ><<<dim3(D2 / 128, BATCH / 128), blk>>>(
        h1, W2, b2, h2, BATCH, D2, D1);
    sgemm_bias<128, 128, 8, 8, 8, true ><<<dim3(D3 / 128, BATCH / 128), blk>>>(
        h2, W3, b3, h3, BATCH, D3, D2);
    sgemm_bias<128, 128, 8, 8, 8, false><<<dim3((DOUT + 127) / 128, BATCH / 128), blk>>>(
        h3, W4, b4, t1, BATCH, DOUT, D3);

    postproc_kernel<<<BATCH, 128>>>(t1, thN, out);
    quad_kernel<<<BATCH, 512>>>(Tr, Ti, thN, out);
}

// round 2
// speedup vs baseline: 1.1507x; 1.1507x over previous
#include <cuda_runtime.h>
#include <math.h>

// ---------------- problem constants ----------------
#define BATCH 2048
#define NC    4
#define NRIS  100
#define DIN   303
#define D1    1024
#define D2    1024
#define D3    512
#define DOUT  264
#define INV_THRESH 1.0e15f

// ---------------- scratch ----------------
__device__ float g_h1[BATCH * D1];
__device__ float g_h2[BATCH * D2];
__device__ float g_h3[BATCH * D3];
__device__ float g_t1[BATCH * DOUT];
__device__ float g_thetaN[BATCH * 2 * NRIS];

// ---------------- packed fp32x2 helpers (sm_103a FFMA2 path) ----------------
__device__ __forceinline__ unsigned long long pk2(float lo, float hi) {
    unsigned long long r;
    asm("mov.b64 %0, {%1, %2};" : "=l"(r) : "f"(lo), "f"(hi));
    return r;
}
__device__ __forceinline__ unsigned long long pkb(float x) {
    unsigned long long r;
    asm("mov.b64 %0, {%1, %1};" : "=l"(r) : "f"(x));
    return r;
}
__device__ __forceinline__ void fma2(unsigned long long& d,
                                     unsigned long long a,
                                     unsigned long long b) {
    asm("fma.rn.f32x2 %0, %1, %2, %3;" : "=l"(d) : "l"(a), "l"(b), "l"(d));
}
__device__ __forceinline__ void unpk2(unsigned long long v, float& lo, float& hi) {
    asm("mov.b64 {%0, %1}, %2;" : "=f"(lo), "=f"(hi) : "l"(v));
}

// ---------------- fp32x2 tiled GEMM + bias (+ optional ReLU) ----------------
// A: [M,K] row-major, W: [K,N] row-major, C: [M,N].
// Accumulators are packed pairs along M (adjacent rows). TN == 4.
template <int BM, int BN, int BK, int TM, bool RELU>
__global__ __launch_bounds__(256) void sgemm_f32x2(
    const float* __restrict__ A, const float* __restrict__ W,
    const float* __restrict__ bias, float* __restrict__ Cmat,
    int M, int N, int K)
{
    constexpr int TN = 4;
    __shared__ float As[BK][BM + 4];   // [k][m], +4 pad -> 2-way store conflict max
    __shared__ float Bs[BK][BN];       // [k][n]

    const int tid = threadIdx.x;
    const int bm  = blockIdx.y * BM;
    const int bn  = blockIdx.x * BN;
    const int tx  = tid % (BN / TN);   // 16
    const int ty  = tid / (BN / TN);   // 16

    unsigned long long acc[TN][TM / 2];
#pragma unroll
    for (int j = 0; j < TN; j++)
#pragma unroll
        for (int i = 0; i < TM / 2; i++) acc[j][i] = 0ull;

    for (int k0 = 0; k0 < K; k0 += BK) {
        // load A tile (transposed into As[k][m])
#pragma unroll
        for (int i = 0; i < (BM * BK) / 256; i++) {
            int idx = tid + i * 256;
            int m  = idx / BK;
            int kk = idx % BK;
            int gm = bm + m, gk = k0 + kk;
            float v = 0.f;
            if (gk < K) v = A[(size_t)gm * K + gk];   // M always divisible by BM
            As[kk][m] = v;
        }
        // load W tile
#pragma unroll
        for (int i = 0; i < (BK * BN) / 256; i++) {
            int idx = tid + i * 256;
            int kk = idx / BN;
            int n  = idx % BN;
            int gk = k0 + kk, gn = bn + n;
            float v = 0.f;
            if (gk < K && gn < N) v = W[(size_t)gk * N + gn];
            Bs[kk][n] = v;
        }
        __syncthreads();

#pragma unroll
        for (int kk = 0; kk < BK; kk++) {
            // A: TM consecutive rows -> TM/2 packed pairs (LDS.128, pairs free)
            unsigned long long ap[TM / 2];
            const float4* A4 = reinterpret_cast<const float4*>(&As[kk][ty * TM]);
#pragma unroll
            for (int q = 0; q < TM / 4; q++) {
                float4 av = A4[q];
                ap[q * 2 + 0] = pk2(av.x, av.y);
                ap[q * 2 + 1] = pk2(av.z, av.w);
            }
            // B: 4 scalars broadcast-packed
            const float4* B4 = reinterpret_cast<const float4*>(&Bs[kk][tx * TN]);
            float4 bv = B4[0];
            unsigned long long bp0 = pkb(bv.x), bp1 = pkb(bv.y),
                               bp2 = pkb(bv.z), bp3 = pkb(bv.w);
#pragma unroll
            for (int ii = 0; ii < TM / 2; ii++) {
                fma2(acc[0][ii], ap[ii], bp0);
                fma2(acc[1][ii], ap[ii], bp1);
                fma2(acc[2][ii], ap[ii], bp2);
                fma2(acc[3][ii], ap[ii], bp3);
            }
        }
        __syncthreads();
    }

#pragma unroll
    for (int j = 0; j < TN; j++) {
        int gn = bn + tx * TN + j;
        if (gn >= N) continue;
        float bv = bias[gn];
#pragma unroll
        for (int ii = 0; ii < TM / 2; ii++) {
            float lo, hi;
            unpk2(acc[j][ii], lo, hi);
            int gm = bm + ty * TM + ii * 2;
            float v0 = lo + bv, v1 = hi + bv;
            if (RELU) { v0 = fmaxf(v0, 0.f); v1 = fmaxf(v1, 0.f); }
            Cmat[(size_t)gm * N + gn]       = v0;
            Cmat[(size_t)(gm + 1) * N + gn] = v1;
        }
    }
}

// ---------------- postprocess: unit-modulus theta + precoder normalization --
__global__ __launch_bounds__(128) void postproc_kernel(
    const float* __restrict__ t1, float* __restrict__ thetaN,
    float* __restrict__ out)
{
    const int b   = blockIdx.x;
    const int tid = threadIdx.x;
    const float* row  = t1  + (size_t)b * DOUT;
    float*       orow = out + (size_t)b * DOUT;

    __shared__ float s[2];

    if (tid < NRIS) {
        float re = row[tid];
        float im = row[NRIS + tid];
        float inv = rsqrtf(re * re + im * im);
        thetaN[(size_t)b * 200 + tid]       = re * inv;
        thetaN[(size_t)b * 200 + 100 + tid] = im * inv;
    }

    int w = tid >> 5, l = tid & 31;
    if (w < 2) {
        int base = 200 + 32 * w;
        float v = 0.f;
        if (l < 16) {
            float re = row[base + l];
            float im = row[base + 16 + l];
            v = re * re + im * im;
        }
#pragma unroll
        for (int o = 8; o; o >>= 1) v += __shfl_down_sync(0xffffffffu, v, o);
        if (l == 0) s[w] = sqrtf(2.0f / v);
    }
    __syncthreads();

    if (tid < 64) {
        int col  = 200 + tid;
        float sc = (tid < 32) ? s[0] : s[1];
        orow[col] = row[col] * sc;
    }
}

// ---------------- quadratic form + rescale: HBM-bound streaming -------------
__global__ __launch_bounds__(512) void quad_kernel(
    const float* __restrict__ Tr, const float* __restrict__ Ti,
    const float* __restrict__ thetaN, float* __restrict__ out)
{
    const int b   = blockIdx.x;
    const int tid = threadIdx.x;

    __shared__ float sth[200];
    __shared__ float partial[16];
    __shared__ float sccc[4];
    __shared__ float sscale;

    if (tid < 200) sth[tid] = thetaN[(size_t)b * 200 + tid];
    __syncthreads();

    const int c  = tid >> 7;
    const int lt = tid & 127;

    const float4* TrV = (const float4*)(Tr + ((size_t)b * NC + c) * 10000);
    const float4* TiV = (const float4*)(Ti + ((size_t)b * NC + c) * 10000);

    float acc = 0.f;
    for (int i = lt; i < 2500; i += 128) {
        int n  = i / 25;
        int m0 = (i - n * 25) * 4;
        float4 tr = TrV[i];
        float4 ti = TiV[i];
        float an = sth[n], bn = sth[100 + n];
        float am, bm;
        am = sth[m0 + 0]; bm = sth[100 + m0 + 0];
        acc += tr.x * (an * am + bn * bm) - ti.x * (an * bm - bn * am);
        am = sth[m0 + 1]; bm = sth[100 + m0 + 1];
        acc += tr.y * (an * am + bn * bm) - ti.y * (an * bm - bn * am);
        am = sth[m0 + 2]; bm = sth[100 + m0 + 2];
        acc += tr.z * (an * am + bn * bm) - ti.z * (an * bm - bn * am);
        am = sth[m0 + 3]; bm = sth[100 + m0 + 3];
        acc += tr.w * (an * am + bn * bm) - ti.w * (an * bm - bn * am);
    }

#pragma unroll
    for (int o = 16; o; o >>= 1) acc += __shfl_down_sync(0xffffffffu, acc, o);
    if ((tid & 31) == 0) partial[tid >> 5] = acc;
    __syncthreads();

    if (tid < 4) {
        float s = partial[tid * 4] + partial[tid * 4 + 1] +
                  partial[tid * 4 + 2] + partial[tid * 4 + 3];
        sccc[tid] = s * INV_THRESH;
    }
    __syncthreads();
    if (tid == 0) {
        float mx = fmaxf(fmaxf(sccc[0], sccc[1]), fmaxf(sccc[2], sccc[3]));
        sscale = rsqrtf(fmaxf(mx, 1.0f));
    }
    __syncthreads();

    if (tid < 200) out[(size_t)b * DOUT + tid] = sth[tid] * sscale;
}

// ---------------- launch ----------------------------------------------------
extern "C" void kernel_launch(void* const* d_in, const int* in_sizes, int n_in,
                              void* d_out, int out_size)
{
    const float* X  = (const float*)d_in[0];
    const float* Tr = (const float*)d_in[1];
    const float* Ti = (const float*)d_in[2];
    const float* W1 = (const float*)d_in[3];
    const float* b1 = (const float*)d_in[4];
    const float* W2 = (const float*)d_in[5];
    const float* b2 = (const float*)d_in[6];
    const float* W3 = (const float*)d_in[7];
    const float* b3 = (const float*)d_in[8];
    const float* W4 = (const float*)d_in[9];
    const float* b4 = (const float*)d_in[10];
    float* out = (float*)d_out;

    float *h1, *h2, *h3, *t1, *thN;
    cudaGetSymbolAddress((void**)&h1,  g_h1);
    cudaGetSymbolAddress((void**)&h2,  g_h2);
    cudaGetSymbolAddress((void**)&h3,  g_h3);
    cudaGetSymbolAddress((void**)&t1,  g_t1);
    cudaGetSymbolAddress((void**)&thN, g_thetaN);

    dim3 blk(256);
    // L1: 2048x1024x303, 128x64 tiles -> 256 blocks
    sgemm_f32x2<128, 64, 16, 8, true ><<<dim3(D1 / 64, BATCH / 128), blk>>>(
        X, W1, b1, h1, BATCH, D1, DIN);
    // L2: 2048x1024x1024 -> 256 blocks
    sgemm_f32x2<128, 64, 16, 8, true ><<<dim3(D2 / 64, BATCH / 128), blk>>>(
        h1, W2, b2, h2, BATCH, D2, D1);
    // L3: 2048x512x1024, 64x64 tiles -> 256 blocks
    sgemm_f32x2<64, 64, 16, 4, true ><<<dim3(D3 / 64, BATCH / 64), blk>>>(
        h2, W3, b3, h3, BATCH, D3, D2);
    // L4: 2048x264x512 -> 160 blocks
    sgemm_f32x2<64, 64, 16, 4, false><<<dim3((DOUT + 63) / 64, BATCH / 64), blk>>>(
        h3, W4, b4, t1, BATCH, DOUT, D3);

    postproc_kernel<<<BATCH, 128>>>(t1, thN, out);
    quad_kernel<<<BATCH, 512>>>(Tr, Ti, thN, out);
}

// round 4
// speedup vs baseline: 2.5735x; 2.2365x over previous
#include <cuda_runtime.h>
#include <cuda_bf16.h>
#include <stdint.h>
#include <math.h>

// ---------------- problem constants ----------------
#define BATCH 2048
#define NC    4
#define NRIS  100
#define DIN   303
#define D1    1024
#define D2    1024
#define D3    512
#define DOUT  264
#define INV_THRESH 1.0e15f

#define KP1 320   // DIN padded to multiple of 64
#define KP2 1024
#define KP3 1024
#define KP4 512

// ---------------- scratch ----------------
__device__ float g_h1[BATCH * D1];
__device__ float g_h2[BATCH * D2];
__device__ float g_h3[BATCH * D3];
__device__ float g_t1[BATCH * DOUT];
__device__ float g_thetaN[BATCH * 2 * NRIS];

// split weights, transposed to [N, Kp] bf16, hi/lo parts
__device__ __nv_bfloat16 g_W1h[D1 * KP1], g_W1l[D1 * KP1];
__device__ __nv_bfloat16 g_W2h[D2 * KP2], g_W2l[D2 * KP2];
__device__ __nv_bfloat16 g_W3h[D3 * KP3], g_W3l[D3 * KP3];
__device__ __nv_bfloat16 g_W4h[DOUT * KP4], g_W4l[DOUT * KP4];

// ---------------- low-level helpers ----------------
__device__ __forceinline__ uint32_t s2u(const void* p) {
    uint32_t a;
    asm("{ .reg .u64 t; cvta.to.shared.u64 t, %1; cvt.u32.u64 %0, t; }"
        : "=r"(a) : "l"(p));
    return a;
}

__device__ __forceinline__ void ldsm_x4(uint32_t* r, uint32_t addr) {
    asm volatile("ldmatrix.sync.aligned.m8n8.x4.shared.b16 {%0,%1,%2,%3}, [%4];"
                 : "=r"(r[0]), "=r"(r[1]), "=r"(r[2]), "=r"(r[3]) : "r"(addr));
}
__device__ __forceinline__ void ldsm_x2(uint32_t* r, uint32_t addr) {
    asm volatile("ldmatrix.sync.aligned.m8n8.x2.shared.b16 {%0,%1}, [%2];"
                 : "=r"(r[0]), "=r"(r[1]) : "r"(addr));
}
__device__ __forceinline__ void mma16816(float* d, const uint32_t* a,
                                         const uint32_t* b) {
    asm volatile(
        "mma.sync.aligned.m16n8k16.row.col.f32.bf16.bf16.f32 "
        "{%0,%1,%2,%3}, {%4,%5,%6,%7}, {%8,%9}, {%0,%1,%2,%3};"
        : "+f"(d[0]), "+f"(d[1]), "+f"(d[2]), "+f"(d[3])
        : "r"(a[0]), "r"(a[1]), "r"(a[2]), "r"(a[3]), "r"(b[0]), "r"(b[1]));
}
__device__ __forceinline__ void cp16(uint32_t dst, const void* src, bool pred) {
    int sz = pred ? 16 : 0;
    asm volatile("cp.async.cg.shared.global [%0], [%1], 16, %2;"
                 :: "r"(dst), "l"(src), "r"(sz));
}
#define CP_COMMIT() asm volatile("cp.async.commit_group;" ::: "memory")
#define CP_WAIT(n)  asm volatile("cp.async.wait_group %0;" :: "n"(n) : "memory")

__device__ __forceinline__ uint32_t pack_bf16(float lo, float hi) {
    uint32_t r;
    asm("cvt.rn.bf16x2.f32 %0, %1, %2;" : "=r"(r) : "f"(hi), "f"(lo));
    return r;
}

#define SWZ(b) ((b) ^ (((b) >> 3) & 0x70))

// smem buffer layout: 2 stages x (Ah, Al, Bh, Bl) of 16KB each
#define OF_AH(s) ((uint32_t)((s) * 65536 + 0))
#define OF_AL(s) ((uint32_t)((s) * 65536 + 16384))
#define OF_BH(s) ((uint32_t)((s) * 65536 + 32768))
#define OF_BL(s) ((uint32_t)((s) * 65536 + 49152))
#define SMEM_GEMM 131072

// ---------------- weight transpose + bf16 split -----------------------------
__global__ __launch_bounds__(256) void split_transpose(
    const float* __restrict__ W, __nv_bfloat16* __restrict__ Wh,
    __nv_bfloat16* __restrict__ Wl, int K, int N, int Kp)
{
    __shared__ float tile[32][33];
    int k0 = blockIdx.x * 32, n0 = blockIdx.y * 32;
    int tx = threadIdx.x % 32, ty = threadIdx.x / 32;

#pragma unroll
    for (int i = 0; i < 4; i++) {
        int k = k0 + ty + i * 8;
        int n = n0 + tx;
        tile[ty + i * 8][tx] = (k < K && n < N) ? W[(size_t)k * N + n] : 0.f;
    }
    __syncthreads();
#pragma unroll
    for (int i = 0; i < 4; i++) {
        int n = n0 + ty + i * 8;
        int k = k0 + tx;
        if (n < N && k < Kp) {
            float v = tile[tx][ty + i * 8];
            __nv_bfloat16 h = __float2bfloat16(v);
            float r = v - __bfloat162float(h);
            Wh[(size_t)n * Kp + k] = h;
            Wl[(size_t)n * Kp + k] = __float2bfloat16(r);
        }
    }
}

// ---------------- mma.sync bf16-split GEMM ----------------------------------
// C[M,N] = relu?(A[M,K]fp32 @ W^T + bias), W split as Wh/Wl [N,Kp] bf16.
// CTA tile 128x128, BK=64, 8 warps (4 along M x 2 along N), warp tile 32x64.
// 3 passes: Ah*Bh + Al*Bh + Ah*Bl. Double-buffered smem.
__global__ __launch_bounds__(256) void gemm_mma(
    const float* __restrict__ A,
    const __nv_bfloat16* __restrict__ Wh,
    const __nv_bfloat16* __restrict__ Wl,
    const float* __restrict__ bias, float* __restrict__ C,
    int M, int N, int K, int Kp, int relu, int kaligned)
{
    extern __shared__ char smem[];
    const uint32_t sb = s2u(smem);
    const int tid  = threadIdx.x;
    const int lane = tid & 31;
    const int wid  = tid >> 5;
    const int wm   = wid & 3;        // M warp: 0..3 -> 32*wm
    const int wn   = wid >> 2;       // N warp: 0..1 -> 64*wn
    const int m0 = blockIdx.y * 128;
    const int n0 = blockIdx.x * 128;
    const int nch = Kp >> 6;

    float acc[2][8][4];
#pragma unroll
    for (int mt = 0; mt < 2; mt++)
#pragma unroll
        for (int nt = 0; nt < 8; nt++)
#pragma unroll
            for (int e = 0; e < 4; e++) acc[mt][nt][e] = 0.f;

    float av[4][8];   // A prefetch registers (4 groups x 8 fp32)

    // ---- staging helpers (inlined as lambdas) ----
    auto ldgA = [&](int c) {
        const int kk0 = c * 64;
#pragma unroll
        for (int g = 0; g < 4; g++) {
            int t = tid + g * 256;
            int m = t >> 3, j = t & 7;
            const float* ap = A + (size_t)(m0 + m) * K + kk0 + j * 8;
            if (kaligned) {
                float4 p0 = *(const float4*)ap;
                float4 p1 = *(const float4*)(ap + 4);
                av[g][0] = p0.x; av[g][1] = p0.y; av[g][2] = p0.z; av[g][3] = p0.w;
                av[g][4] = p1.x; av[g][5] = p1.y; av[g][6] = p1.z; av[g][7] = p1.w;
            } else {
#pragma unroll
                for (int e = 0; e < 8; e++)
                    av[g][e] = (kk0 + j * 8 + e < K) ? ap[e] : 0.f;
            }
        }
    };
    auto stsA = [&](int c) {
        const int s = c & 1;
#pragma unroll
        for (int g = 0; g < 4; g++) {
            int t = tid + g * 256;
            int m = t >> 3, j = t & 7;
            uint32_t hp[4], lp[4];
#pragma unroll
            for (int q = 0; q < 4; q++) {
                float v0 = av[g][2 * q], v1 = av[g][2 * q + 1];
                __nv_bfloat16 h0 = __float2bfloat16(v0);
                __nv_bfloat16 h1 = __float2bfloat16(v1);
                float r0 = v0 - __bfloat162float(h0);
                float r1 = v1 - __bfloat162float(h1);
                hp[q] = (uint32_t)__bfloat16_as_ushort(h0) |
                        ((uint32_t)__bfloat16_as_ushort(h1) << 16);
                lp[q] = pack_bf16(__bfloat162float(__float2bfloat16(r0)),
                                  __bfloat162float(__float2bfloat16(r1)));
            }
            uint32_t sw = SWZ((uint32_t)(m * 128 + j * 16));
            *(uint4*)(smem + OF_AH(s) + sw) = make_uint4(hp[0], hp[1], hp[2], hp[3]);
            *(uint4*)(smem + OF_AL(s) + sw) = make_uint4(lp[0], lp[1], lp[2], lp[3]);
        }
    };
    auto stageB = [&](int c) {
        const int s = c & 1;
        const int kk0 = c * 64;
#pragma unroll
        for (int g = 0; g < 4; g++) {
            int t = tid + g * 256;
            int n = t >> 3, j = t & 7;
            bool ok = (n0 + n) < N;
            int row = ok ? (n0 + n) : 0;
            uint32_t sw = SWZ((uint32_t)(n * 128 + j * 16));
            cp16(sb + OF_BH(s) + sw, Wh + (size_t)row * Kp + kk0 + j * 8, ok);
            cp16(sb + OF_BL(s) + sw, Wl + (size_t)row * Kp + kk0 + j * 8, ok);
        }
    };

    // per-thread ldmatrix intra-tile coordinates
    const int qa = lane >> 3;
    const uint32_t rowA = (uint32_t)(wm * 32 + (qa & 1) * 8 + (lane & 7));
    const uint32_t kaOff = (uint32_t)((qa >> 1) * 16);
    const uint32_t rowB = (uint32_t)(wn * 64 + (lane & 7));
    const uint32_t kbOff = (uint32_t)(((lane >> 3) & 1) * 16);

    auto compute = [&](int c) {
        const int s = c & 1;
        const uint32_t bAh = sb + OF_AH(s), bAl = sb + OF_AL(s);
        const uint32_t bBh = sb + OF_BH(s), bBl = sb + OF_BL(s);
#pragma unroll
        for (int s16 = 0; s16 < 4; s16++) {
            uint32_t a_h[2][4], a_l[2][4];
#pragma unroll
            for (int mt = 0; mt < 2; mt++) {
                uint32_t off = SWZ((rowA + mt * 16) * 128 + s16 * 32 + kaOff);
                ldsm_x4(a_h[mt], bAh + off);
                ldsm_x4(a_l[mt], bAl + off);
            }
            uint32_t b_h[8][2], b_l[8][2];
#pragma unroll
            for (int nt = 0; nt < 8; nt++) {
                uint32_t off = SWZ((rowB + nt * 8) * 128 + s16 * 32 + kbOff);
                ldsm_x2(b_h[nt], bBh + off);
                ldsm_x2(b_l[nt], bBl + off);
            }
#pragma unroll
            for (int mt = 0; mt < 2; mt++)
#pragma unroll
                for (int nt = 0; nt < 8; nt++) {
                    mma16816(acc[mt][nt], a_h[mt], b_h[nt]);
                    mma16816(acc[mt][nt], a_l[mt], b_h[nt]);
                    mma16816(acc[mt][nt], a_h[mt], b_l[nt]);
                }
        }
    };

    // ---- pipelined mainloop ----
    stageB(0); CP_COMMIT();
    ldgA(0);
    stsA(0);

    for (int c = 0; c < nch; c++) {
        if (c + 1 < nch) {
            ldgA(c + 1);
            stageB(c + 1); CP_COMMIT();
            CP_WAIT(1);
        } else {
            CP_WAIT(0);
        }
        __syncthreads();
        compute(c);
        if (c + 1 < nch) stsA(c + 1);
        __syncthreads();
    }

    // ---- epilogue ----
#pragma unroll
    for (int mt = 0; mt < 2; mt++) {
        int r0 = m0 + wm * 32 + mt * 16 + (lane >> 2);
#pragma unroll
        for (int nt = 0; nt < 8; nt++) {
            int col = n0 + wn * 64 + nt * 8 + (lane & 3) * 2;
            if (col >= N) continue;
            float2 bv = *(const float2*)(bias + col);
            float o0 = acc[mt][nt][0] + bv.x;
            float o1 = acc[mt][nt][1] + bv.y;
            float o2 = acc[mt][nt][2] + bv.x;
            float o3 = acc[mt][nt][3] + bv.y;
            if (relu) {
                o0 = fmaxf(o0, 0.f); o1 = fmaxf(o1, 0.f);
                o2 = fmaxf(o2, 0.f); o3 = fmaxf(o3, 0.f);
            }
            *(float2*)(C + (size_t)r0 * N + col)       = make_float2(o0, o1);
            *(float2*)(C + (size_t)(r0 + 8) * N + col) = make_float2(o2, o3);
        }
    }
}

// ---------------- postprocess: unit-modulus theta + precoder normalization --
__global__ __launch_bounds__(128) void postproc_kernel(
    const float* __restrict__ t1, float* __restrict__ thetaN,
    float* __restrict__ out)
{
    const int b   = blockIdx.x;
    const int tid = threadIdx.x;
    const float* row  = t1  + (size_t)b * DOUT;
    float*       orow = out + (size_t)b * DOUT;

    __shared__ float s[2];

    if (tid < NRIS) {
        float re = row[tid];
        float im = row[NRIS + tid];
        float inv = rsqrtf(re * re + im * im);
        thetaN[(size_t)b * 200 + tid]       = re * inv;
        thetaN[(size_t)b * 200 + 100 + tid] = im * inv;
    }

    int w = tid >> 5, l = tid & 31;
    if (w < 2) {
        int base = 200 + 32 * w;
        float v = 0.f;
        if (l < 16) {
            float re = row[base + l];
            float im = row[base + 16 + l];
            v = re * re + im * im;
        }
#pragma unroll
        for (int o = 8; o; o >>= 1) v += __shfl_down_sync(0xffffffffu, v, o);
        if (l == 0) s[w] = sqrtf(2.0f / v);
    }
    __syncthreads();

    if (tid < 64) {
        int col  = 200 + tid;
        float sc = (tid < 32) ? s[0] : s[1];
        orow[col] = row[col] * sc;
    }
}

// ---------------- quadratic form + rescale: HBM-bound streaming -------------
__global__ __launch_bounds__(512) void quad_kernel(
    const float* __restrict__ Tr, const float* __restrict__ Ti,
    const float* __restrict__ thetaN, float* __restrict__ out)
{
    const int b   = blockIdx.x;
    const int tid = threadIdx.x;

    __shared__ float sth[200];
    __shared__ float partial[16];
    __shared__ float sccc[4];
    __shared__ float sscale;

    if (tid < 200) sth[tid] = thetaN[(size_t)b * 200 + tid];
    __syncthreads();

    const int c  = tid >> 7;
    const int lt = tid & 127;

    const float4* TrV = (const float4*)(Tr + ((size_t)b * NC + c) * 10000);
    const float4* TiV = (const float4*)(Ti + ((size_t)b * NC + c) * 10000);

    float acc = 0.f;
    for (int i = lt; i < 2500; i += 128) {
        int n  = i / 25;
        int m0 = (i - n * 25) * 4;
        float4 tr = TrV[i];
        float4 ti = TiV[i];
        float an = sth[n], bn = sth[100 + n];
        float am, bm;
        am = sth[m0 + 0]; bm = sth[100 + m0 + 0];
        acc += tr.x * (an * am + bn * bm) - ti.x * (an * bm - bn * am);
        am = sth[m0 + 1]; bm = sth[100 + m0 + 1];
        acc += tr.y * (an * am + bn * bm) - ti.y * (an * bm - bn * am);
        am = sth[m0 + 2]; bm = sth[100 + m0 + 2];
        acc += tr.z * (an * am + bn * bm) - ti.z * (an * bm - bn * am);
        am = sth[m0 + 3]; bm = sth[100 + m0 + 3];
        acc += tr.w * (an * am + bn * bm) - ti.w * (an * bm - bn * am);
    }

#pragma unroll
    for (int o = 16; o; o >>= 1) acc += __shfl_down_sync(0xffffffffu, acc, o);
    if ((tid & 31) == 0) partial[tid >> 5] = acc;
    __syncthreads();

    if (tid < 4) {
        float s = partial[tid * 4] + partial[tid * 4 + 1] +
                  partial[tid * 4 + 2] + partial[tid * 4 + 3];
        sccc[tid] = s * INV_THRESH;
    }
    __syncthreads();
    if (tid == 0) {
        float mx = fmaxf(fmaxf(sccc[0], sccc[1]), fmaxf(sccc[2], sccc[3]));
        sscale = rsqrtf(fmaxf(mx, 1.0f));
    }
    __syncthreads();

    if (tid < 200) out[(size_t)b * DOUT + tid] = sth[tid] * sscale;
}

// ---------------- launch ----------------------------------------------------
extern "C" void kernel_launch(void* const* d_in, const int* in_sizes, int n_in,
                              void* d_out, int out_size)
{
    const float* X  = (const float*)d_in[0];
    const float* Tr = (const float*)d_in[1];
    const float* Ti = (const float*)d_in[2];
    const float* W1 = (const float*)d_in[3];
    const float* b1 = (const float*)d_in[4];
    const float* W2 = (const float*)d_in[5];
    const float* b2 = (const float*)d_in[6];
    const float* W3 = (const float*)d_in[7];
    const float* b3 = (const float*)d_in[8];
    const float* W4 = (const float*)d_in[9];
    const float* b4 = (const float*)d_in[10];
    float* out = (float*)d_out;

    float *h1, *h2, *h3, *t1, *thN;
    cudaGetSymbolAddress((void**)&h1,  g_h1);
    cudaGetSymbolAddress((void**)&h2,  g_h2);
    cudaGetSymbolAddress((void**)&h3,  g_h3);
    cudaGetSymbolAddress((void**)&t1,  g_t1);
    cudaGetSymbolAddress((void**)&thN, g_thetaN);

    __nv_bfloat16 *w1h, *w1l, *w2h, *w2l, *w3h, *w3l, *w4h, *w4l;
    cudaGetSymbolAddress((void**)&w1h, g_W1h);
    cudaGetSymbolAddress((void**)&w1l, g_W1l);
    cudaGetSymbolAddress((void**)&w2h, g_W2h);
    cudaGetSymbolAddress((void**)&w2l, g_W2l);
    cudaGetSymbolAddress((void**)&w3h, g_W3h);
    cudaGetSymbolAddress((void**)&w3l, g_W3l);
    cudaGetSymbolAddress((void**)&w4h, g_W4h);
    cudaGetSymbolAddress((void**)&w4l, g_W4l);

    cudaFuncSetAttribute(gemm_mma, cudaFuncAttributeMaxDynamicSharedMemorySize,
                         SMEM_GEMM);

    dim3 tb(256);
    split_transpose<<<dim3(KP1 / 32, D1 / 32), tb>>>(W1, w1h, w1l, DIN, D1, KP1);
    split_transpose<<<dim3(KP2 / 32, D2 / 32), tb>>>(W2, w2h, w2l, D1, D2, KP2);
    split_transpose<<<dim3(KP3 / 32, D3 / 32), tb>>>(W3, w3h, w3l, D2, D3, KP3);
    split_transpose<<<dim3(KP4 / 32, (DOUT + 31) / 32), tb>>>(W4, w4h, w4l, D3, DOUT, KP4);

    gemm_mma<<<dim3(D1 / 128, BATCH / 128), 256, SMEM_GEMM>>>(
        X, w1h, w1l, b1, h1, BATCH, D1, DIN, KP1, 1, 0);
    gemm_mma<<<dim3(D2 / 128, BATCH / 128), 256, SMEM_GEMM>>>(
        h1, w2h, w2l, b2, h2, BATCH, D2, D1, KP2, 1, 1);
    gemm_mma<<<dim3(D3 / 128, BATCH / 128), 256, SMEM_GEMM>>>(
        h2, w3h, w3l, b3, h3, BATCH, D3, D2, KP3, 1, 1);
    gemm_mma<<<dim3((DOUT + 127) / 128, BATCH / 128), 256, SMEM_GEMM>>>(
        h3, w4h, w4l, b4, t1, BATCH, DOUT, D3, KP4, 0, 1);

    postproc_kernel<<<BATCH, 128>>>(t1, thN, out);
    quad_kernel<<<BATCH, 512>>>(Tr, Ti, thN, out);
}

// round 5
// speedup vs baseline: 3.1781x; 1.2349x over previous
#include <cuda_runtime.h>
#include <cuda_bf16.h>
#include <stdint.h>
#include <math.h>

// ---------------- problem constants ----------------
#define BATCH 2048
#define NC    4
#define NRIS  100
#define DIN   303
#define D1    1024
#define D2    1024
#define D3    512
#define DOUT  264
#define INV_THRESH 1.0e15f

#define KP1 320
#define KP2 1024
#define KP3 1024
#define KP4 512

// ---------------- scratch ----------------
__device__ float g_h1[BATCH * D1];
__device__ float g_h2[BATCH * D2];
__device__ float g_h3[BATCH * D3];
__device__ float g_t1[BATCH * DOUT];
__device__ float g_thetaN[BATCH * 2 * NRIS];
__device__ float g_ccc[BATCH * NC];

__device__ __nv_bfloat16 g_W1h[D1 * KP1], g_W1l[D1 * KP1];
__device__ __nv_bfloat16 g_W2h[D2 * KP2], g_W2l[D2 * KP2];
__device__ __nv_bfloat16 g_W3h[D3 * KP3], g_W3l[D3 * KP3];
__device__ __nv_bfloat16 g_W4h[DOUT * KP4], g_W4l[DOUT * KP4];

// ---------------- low-level helpers ----------------
__device__ __forceinline__ uint32_t s2u(const void* p) {
    uint32_t a;
    asm("{ .reg .u64 t; cvta.to.shared.u64 t, %1; cvt.u32.u64 %0, t; }"
        : "=r"(a) : "l"(p));
    return a;
}
__device__ __forceinline__ void ldsm_x4(uint32_t* r, uint32_t addr) {
    asm volatile("ldmatrix.sync.aligned.m8n8.x4.shared.b16 {%0,%1,%2,%3}, [%4];"
                 : "=r"(r[0]), "=r"(r[1]), "=r"(r[2]), "=r"(r[3]) : "r"(addr));
}
__device__ __forceinline__ void mma16816(float* d, const uint32_t* a,
                                         const uint32_t* b) {
    asm volatile(
        "mma.sync.aligned.m16n8k16.row.col.f32.bf16.bf16.f32 "
        "{%0,%1,%2,%3}, {%4,%5,%6,%7}, {%8,%9}, {%0,%1,%2,%3};"
        : "+f"(d[0]), "+f"(d[1]), "+f"(d[2]), "+f"(d[3])
        : "r"(a[0]), "r"(a[1]), "r"(a[2]), "r"(a[3]), "r"(b[0]), "r"(b[1]));
}
__device__ __forceinline__ void cp16(uint32_t dst, const void* src, bool pred) {
    int sz = pred ? 16 : 0;
    asm volatile("cp.async.cg.shared.global [%0], [%1], 16, %2;"
                 :: "r"(dst), "l"(src), "r"(sz));
}
#define CP_COMMIT() asm volatile("cp.async.commit_group;" ::: "memory")
#define CP_WAIT(n)  asm volatile("cp.async.wait_group %0;" :: "n"(n) : "memory")

__device__ __forceinline__ uint32_t pack_bf16(float lo, float hi) {
    uint32_t r;
    asm("cvt.rn.bf16x2.f32 %0, %1, %2;" : "=r"(r) : "f"(hi), "f"(lo));
    return r;
}
#define SWZ(b) ((b) ^ (((b) >> 3) & 0x70))

// ---------------- fused weight transpose + bf16 split -----------------------
#define NBX1 (KP1 / 32)
#define NBX2 (KP2 / 32)
#define NBX3 (KP3 / 32)
#define NBX4 (KP4 / 32)
#define NB1 (NBX1 * ((D1 + 31) / 32))
#define NB2 (NBX2 * ((D2 + 31) / 32))
#define NB3 (NBX3 * ((D3 + 31) / 32))
#define NB4 (NBX4 * ((DOUT + 31) / 32))
#define NB_TOTAL (NB1 + NB2 + NB3 + NB4)

__global__ __launch_bounds__(256) void split_transpose_all(
    const float* __restrict__ W1a, const float* __restrict__ W2a,
    const float* __restrict__ W3a, const float* __restrict__ W4a,
    __nv_bfloat16* __restrict__ h1, __nv_bfloat16* __restrict__ l1,
    __nv_bfloat16* __restrict__ h2, __nv_bfloat16* __restrict__ l2,
    __nv_bfloat16* __restrict__ h3, __nv_bfloat16* __restrict__ l3,
    __nv_bfloat16* __restrict__ h4, __nv_bfloat16* __restrict__ l4)
{
    int bid = blockIdx.x;
    const float* W; __nv_bfloat16 *Wh, *Wl;
    int K, N, Kp, nbx, r;
    if (bid < NB1) {
        W = W1a; Wh = h1; Wl = l1; K = DIN; N = D1; Kp = KP1; nbx = NBX1; r = bid;
    } else if (bid < NB1 + NB2) {
        W = W2a; Wh = h2; Wl = l2; K = D1; N = D2; Kp = KP2; nbx = NBX2; r = bid - NB1;
    } else if (bid < NB1 + NB2 + NB3) {
        W = W3a; Wh = h3; Wl = l3; K = D2; N = D3; Kp = KP3; nbx = NBX3; r = bid - NB1 - NB2;
    } else {
        W = W4a; Wh = h4; Wl = l4; K = D3; N = DOUT; Kp = KP4; nbx = NBX4; r = bid - NB1 - NB2 - NB3;
    }
    int k0 = (r % nbx) * 32, n0 = (r / nbx) * 32;

    __shared__ float tile[32][33];
    int tx = threadIdx.x % 32, ty = threadIdx.x / 32;
#pragma unroll
    for (int i = 0; i < 4; i++) {
        int k = k0 + ty + i * 8, n = n0 + tx;
        tile[ty + i * 8][tx] = (k < K && n < N) ? W[(size_t)k * N + n] : 0.f;
    }
    __syncthreads();
#pragma unroll
    for (int i = 0; i < 4; i++) {
        int n = n0 + ty + i * 8, k = k0 + tx;
        if (n < N) {
            float v = tile[tx][ty + i * 8];
            __nv_bfloat16 h = __float2bfloat16(v);
            float rr = v - __bfloat162float(h);
            Wh[(size_t)n * Kp + k] = h;
            Wl[(size_t)n * Kp + k] = __float2bfloat16(rr);
        }
    }
}

// ---------------- mma.sync bf16-split GEMM ----------------------------------
// C[M,N] = relu?(A[M,K]fp32 @ W^T + bias). BM = MW*32, BN = 128.
// 8 warps: MW along M x (8/MW) along N. 3-pass split: AhBh + AlBh + AhBl.
template <int MW>
__global__ __launch_bounds__(256) void gemm_mma(
    const float* __restrict__ A,
    const __nv_bfloat16* __restrict__ Wh,
    const __nv_bfloat16* __restrict__ Wl,
    const float* __restrict__ bias, float* __restrict__ C,
    int M, int N, int K, int Kp, int relu, int kaligned)
{
    constexpr int NW = 8 / MW;         // warps along N
    constexpr int BM = MW * 32;
    constexpr int PN = 128 / NW;       // per-warp N span
    constexpr int NT = PN / 8;         // 8-col tiles per warp
    constexpr int ABYTES = BM * 128;   // one A buffer (h or l)
    constexpr int STAGE  = 2 * ABYTES + 32768;

    extern __shared__ char smem[];
    const uint32_t sb = s2u(smem);
    const int tid  = threadIdx.x;
    const int lane = tid & 31;
    const int wid  = tid >> 5;
    const int wm   = wid % MW;
    const int wn   = wid / MW;
    const int m0 = blockIdx.y * BM;
    const int n0 = blockIdx.x * 128;
    const int nch = Kp >> 6;

    float acc[2][NT][4];
#pragma unroll
    for (int mt = 0; mt < 2; mt++)
#pragma unroll
        for (int nt = 0; nt < NT; nt++)
#pragma unroll
            for (int e = 0; e < 4; e++) acc[mt][nt][e] = 0.f;

    float av[MW][8];

    auto ldgA = [&](int c) {
        const int kk0 = c * 64;
#pragma unroll
        for (int g = 0; g < MW; g++) {
            int t = tid + g * 256;
            int m = t >> 3, j = t & 7;
            const float* ap = A + (size_t)(m0 + m) * K + kk0 + j * 8;
            if (kaligned) {
                float4 p0 = *(const float4*)ap;
                float4 p1 = *(const float4*)(ap + 4);
                av[g][0] = p0.x; av[g][1] = p0.y; av[g][2] = p0.z; av[g][3] = p0.w;
                av[g][4] = p1.x; av[g][5] = p1.y; av[g][6] = p1.z; av[g][7] = p1.w;
            } else {
#pragma unroll
                for (int e = 0; e < 8; e++)
                    av[g][e] = (kk0 + j * 8 + e < K) ? ap[e] : 0.f;
            }
        }
    };
    auto stsA = [&](int c) {
        const uint32_t s = (uint32_t)(c & 1) * STAGE;
#pragma unroll
        for (int g = 0; g < MW; g++) {
            int t = tid + g * 256;
            int m = t >> 3, j = t & 7;
            uint32_t hp[4], lp[4];
#pragma unroll
            for (int q = 0; q < 4; q++) {
                float v0 = av[g][2 * q], v1 = av[g][2 * q + 1];
                __nv_bfloat16 h0 = __float2bfloat16(v0);
                __nv_bfloat16 h1 = __float2bfloat16(v1);
                float r0 = v0 - __bfloat162float(h0);
                float r1 = v1 - __bfloat162float(h1);
                hp[q] = (uint32_t)__bfloat16_as_ushort(h0) |
                        ((uint32_t)__bfloat16_as_ushort(h1) << 16);
                lp[q] = pack_bf16(__bfloat162float(__float2bfloat16(r0)),
                                  __bfloat162float(__float2bfloat16(r1)));
            }
            uint32_t sw = SWZ((uint32_t)(m * 128 + j * 16));
            *(uint4*)(smem + s + sw)          = make_uint4(hp[0], hp[1], hp[2], hp[3]);
            *(uint4*)(smem + s + ABYTES + sw) = make_uint4(lp[0], lp[1], lp[2], lp[3]);
        }
    };
    auto stageB = [&](int c) {
        const uint32_t s = (uint32_t)(c & 1) * STAGE;
        const int kk0 = c * 64;
#pragma unroll
        for (int g = 0; g < 4; g++) {
            int t = tid + g * 256;
            int n = t >> 3, j = t & 7;
            bool ok = (n0 + n) < N;
            int row = ok ? (n0 + n) : 0;
            uint32_t sw = SWZ((uint32_t)(n * 128 + j * 16));
            cp16(sb + s + 2 * ABYTES + sw,         Wh + (size_t)row * Kp + kk0 + j * 8, ok);
            cp16(sb + s + 2 * ABYTES + 16384 + sw, Wl + (size_t)row * Kp + kk0 + j * 8, ok);
        }
    };

    const int qa = lane >> 3;
    const uint32_t rowA  = (uint32_t)(wm * 32 + (qa & 1) * 8 + (lane & 7));
    const uint32_t kaOff = (uint32_t)((qa >> 1) * 16);
    // paired-B ldmatrix.x4 lane map: 2 n-tiles x 2 k-halves
    const uint32_t rowBp = (uint32_t)(wn * PN + ((lane >> 4) & 1) * 8 + (lane & 7));
    const uint32_t kbOff = (uint32_t)(((lane >> 3) & 1) * 16);

    auto compute = [&](int c) {
        const uint32_t s = (uint32_t)(c & 1) * STAGE;
        const uint32_t bAh = sb + s, bAl = sb + s + ABYTES;
        const uint32_t bBh = sb + s + 2 * ABYTES, bBl = bBh + 16384;
#pragma unroll
        for (int s16 = 0; s16 < 4; s16++) {
            uint32_t a_h[2][4], a_l[2][4];
#pragma unroll
            for (int mt = 0; mt < 2; mt++) {
                uint32_t off = SWZ((rowA + mt * 16) * 128 + s16 * 32 + kaOff);
                ldsm_x4(a_h[mt], bAh + off);
                ldsm_x4(a_l[mt], bAl + off);
            }
            uint32_t b_h[NT][2], b_l[NT][2];
#pragma unroll
            for (int ntp = 0; ntp < NT / 2; ntp++) {
                uint32_t off = SWZ((rowBp + ntp * 16) * 128 + s16 * 32 + kbOff);
                uint32_t r4[4];
                ldsm_x4(r4, bBh + off);
                b_h[2 * ntp][0] = r4[0]; b_h[2 * ntp][1] = r4[1];
                b_h[2 * ntp + 1][0] = r4[2]; b_h[2 * ntp + 1][1] = r4[3];
                ldsm_x4(r4, bBl + off);
                b_l[2 * ntp][0] = r4[0]; b_l[2 * ntp][1] = r4[1];
                b_l[2 * ntp + 1][0] = r4[2]; b_l[2 * ntp + 1][1] = r4[3];
            }
#pragma unroll
            for (int mt = 0; mt < 2; mt++)
#pragma unroll
                for (int nt = 0; nt < NT; nt++) {
                    mma16816(acc[mt][nt], a_h[mt], b_h[nt]);
                    mma16816(acc[mt][nt], a_l[mt], b_h[nt]);
                    mma16816(acc[mt][nt], a_h[mt], b_l[nt]);
                }
        }
    };

    stageB(0); CP_COMMIT();
    ldgA(0);
    stsA(0);

    for (int c = 0; c < nch; c++) {
        if (c + 1 < nch) {
            ldgA(c + 1);
            stageB(c + 1); CP_COMMIT();
            CP_WAIT(1);
        } else {
            CP_WAIT(0);
        }
        __syncthreads();
        compute(c);
        if (c + 1 < nch) stsA(c + 1);
        __syncthreads();
    }

#pragma unroll
    for (int mt = 0; mt < 2; mt++) {
        int r0 = m0 + wm * 32 + mt * 16 + (lane >> 2);
#pragma unroll
        for (int nt = 0; nt < NT; nt++) {
            int col = n0 + wn * PN + nt * 8 + (lane & 3) * 2;
            if (col >= N) continue;
            float2 bv = *(const float2*)(bias + col);
            float o0 = acc[mt][nt][0] + bv.x;
            float o1 = acc[mt][nt][1] + bv.y;
            float o2 = acc[mt][nt][2] + bv.x;
            float o3 = acc[mt][nt][3] + bv.y;
            if (relu) {
                o0 = fmaxf(o0, 0.f); o1 = fmaxf(o1, 0.f);
                o2 = fmaxf(o2, 0.f); o3 = fmaxf(o3, 0.f);
            }
            *(float2*)(C + (size_t)r0 * N + col)       = make_float2(o0, o1);
            *(float2*)(C + (size_t)(r0 + 8) * N + col) = make_float2(o2, o3);
        }
    }
}

// ---------------- postprocess: unit-modulus theta + precoder normalization --
__global__ __launch_bounds__(128) void postproc_kernel(
    const float* __restrict__ t1, float* __restrict__ thetaN,
    float* __restrict__ out)
{
    const int b   = blockIdx.x;
    const int tid = threadIdx.x;
    const float* row  = t1  + (size_t)b * DOUT;
    float*       orow = out + (size_t)b * DOUT;

    __shared__ float s[2];

    if (tid < NRIS) {
        float re = row[tid];
        float im = row[NRIS + tid];
        float inv = rsqrtf(re * re + im * im);
        thetaN[(size_t)b * 200 + tid]       = re * inv;
        thetaN[(size_t)b * 200 + 100 + tid] = im * inv;
    }

    int w = tid >> 5, l = tid & 31;
    if (w < 2) {
        int base = 200 + 32 * w;
        float v = 0.f;
        if (l < 16) {
            float re = row[base + l];
            float im = row[base + 16 + l];
            v = re * re + im * im;
        }
#pragma unroll
        for (int o = 8; o; o >>= 1) v += __shfl_down_sync(0xffffffffu, v, o);
        if (l == 0) s[w] = sqrtf(2.0f / v);
    }
    __syncthreads();

    if (tid < 64) {
        int col  = 200 + tid;
        float sc = (tid < 32) ? s[0] : s[1];
        orow[col] = row[col] * sc;
    }
}

// ---------------- quad pass 1: CCC[b][c] = Re(theta^H T_c theta)/thr --------
// One block per (b, c). De-interleaved theta copies -> conflict-light LDS.
__global__ __launch_bounds__(256) void quad_pass1(
    const float* __restrict__ Tr, const float* __restrict__ Ti,
    const float* __restrict__ thetaN, float* __restrict__ ccc)
{
    const int bc = blockIdx.x;
    const int b  = bc >> 2;
    const int tid = threadIdx.x;

    __shared__ float sa[100], sb_[100];
    __shared__ float da[4][32], db[4][32];   // da[e][q] = sa[4q+e]
    __shared__ float wsum[8];

    if (tid < 200) {
        float v = thetaN[(size_t)b * 200 + tid];
        if (tid < 100) {
            sa[tid] = v;
            da[tid & 3][tid >> 2] = v;
        } else {
            int t = tid - 100;
            sb_[t] = v;
            db[t & 3][t >> 2] = v;
        }
    }
    __syncthreads();

    const float4* TrV = (const float4*)(Tr + (size_t)bc * 10000);
    const float4* TiV = (const float4*)(Ti + (size_t)bc * 10000);

    float acc = 0.f;
    for (int i = tid; i < 2500; i += 256) {
        int n = i / 25;
        int q = i - n * 25;
        float4 tr = __ldcs(TrV + i);
        float4 ti = __ldcs(TiV + i);
        float an = sa[n], bn = sb_[n];
        // acc += tr*(an*am + bn*bm) + ti*(bn*am - an*bm)
        {
            float am = da[0][q], bm = db[0][q];
            acc += tr.x * (an * am + bn * bm) + ti.x * (bn * am - an * bm);
        }
        {
            float am = da[1][q], bm = db[1][q];
            acc += tr.y * (an * am + bn * bm) + ti.y * (bn * am - an * bm);
        }
        {
            float am = da[2][q], bm = db[2][q];
            acc += tr.z * (an * am + bn * bm) + ti.z * (bn * am - an * bm);
        }
        {
            float am = da[3][q], bm = db[3][q];
            acc += tr.w * (an * am + bn * bm) + ti.w * (bn * am - an * bm);
        }
    }

#pragma unroll
    for (int o = 16; o; o >>= 1) acc += __shfl_down_sync(0xffffffffu, acc, o);
    if ((tid & 31) == 0) wsum[tid >> 5] = acc;
    __syncthreads();
    if (tid == 0) {
        float s = 0.f;
#pragma unroll
        for (int w = 0; w < 8; w++) s += wsum[w];
        ccc[bc] = s * INV_THRESH;
    }
}

// ---------------- quad pass 2: scale + write theta_hat ----------------------
__global__ __launch_bounds__(256) void quad_pass2(
    const float* __restrict__ ccc, const float* __restrict__ thetaN,
    float* __restrict__ out)
{
    const int b = blockIdx.x;
    const int tid = threadIdx.x;
    float c0 = ccc[b * 4 + 0], c1 = ccc[b * 4 + 1];
    float c2 = ccc[b * 4 + 2], c3 = ccc[b * 4 + 3];
    float mx = fmaxf(fmaxf(c0, c1), fmaxf(c2, c3));
    float scale = rsqrtf(fmaxf(mx, 1.0f));
    if (tid < 200)
        out[(size_t)b * DOUT + tid] = thetaN[(size_t)b * 200 + tid] * scale;
}

// ---------------- launch ----------------------------------------------------
extern "C" void kernel_launch(void* const* d_in, const int* in_sizes, int n_in,
                              void* d_out, int out_size)
{
    const float* X  = (const float*)d_in[0];
    const float* Tr = (const float*)d_in[1];
    const float* Ti = (const float*)d_in[2];
    const float* W1 = (const float*)d_in[3];
    const float* b1 = (const float*)d_in[4];
    const float* W2 = (const float*)d_in[5];
    const float* b2 = (const float*)d_in[6];
    const float* W3 = (const float*)d_in[7];
    const float* b3 = (const float*)d_in[8];
    const float* W4 = (const float*)d_in[9];
    const float* b4 = (const float*)d_in[10];
    float* out = (float*)d_out;

    float *h1, *h2, *h3, *t1, *thN, *ccc;
    cudaGetSymbolAddress((void**)&h1,  g_h1);
    cudaGetSymbolAddress((void**)&h2,  g_h2);
    cudaGetSymbolAddress((void**)&h3,  g_h3);
    cudaGetSymbolAddress((void**)&t1,  g_t1);
    cudaGetSymbolAddress((void**)&thN, g_thetaN);
    cudaGetSymbolAddress((void**)&ccc, g_ccc);

    __nv_bfloat16 *w1h, *w1l, *w2h, *w2l, *w3h, *w3l, *w4h, *w4l;
    cudaGetSymbolAddress((void**)&w1h, g_W1h);
    cudaGetSymbolAddress((void**)&w1l, g_W1l);
    cudaGetSymbolAddress((void**)&w2h, g_W2h);
    cudaGetSymbolAddress((void**)&w2l, g_W2l);
    cudaGetSymbolAddress((void**)&w3h, g_W3h);
    cudaGetSymbolAddress((void**)&w3l, g_W3l);
    cudaGetSymbolAddress((void**)&w4h, g_W4h);
    cudaGetSymbolAddress((void**)&w4l, g_W4l);

    cudaFuncSetAttribute(gemm_mma<4>, cudaFuncAttributeMaxDynamicSharedMemorySize,
                         131072);
    cudaFuncSetAttribute(gemm_mma<2>, cudaFuncAttributeMaxDynamicSharedMemorySize,
                         98304);

    split_transpose_all<<<NB_TOTAL, 256>>>(W1, W2, W3, W4,
                                           w1h, w1l, w2h, w2l,
                                           w3h, w3l, w4h, w4l);

    gemm_mma<4><<<dim3(D1 / 128, BATCH / 128), 256, 131072>>>(
        X, w1h, w1l, b1, h1, BATCH, D1, DIN, KP1, 1, 0);
    gemm_mma<4><<<dim3(D2 / 128, BATCH / 128), 256, 131072>>>(
        h1, w2h, w2l, b2, h2, BATCH, D2, D1, KP2, 1, 1);
    gemm_mma<2><<<dim3(D3 / 128, BATCH / 64), 256, 98304>>>(
        h2, w3h, w3l, b3, h3, BATCH, D3, D2, KP3, 1, 1);
    gemm_mma<2><<<dim3((DOUT + 127) / 128, BATCH / 64), 256, 98304>>>(
        h3, w4h, w4l, b4, t1, BATCH, DOUT, D3, KP4, 0, 1);

    postproc_kernel<<<BATCH, 128>>>(t1, thN, out);
    quad_pass1<<<BATCH * NC, 256>>>(Tr, Ti, thN, ccc);
    quad_pass2<<<BATCH, 256>>>(ccc, thN, out);
}

// round 7
// speedup vs baseline: 3.2801x; 1.0321x over previous
#include <cuda_runtime.h>
#include <cuda_bf16.h>
#include <stdint.h>
#include <math.h>

// ---------------- problem constants ----------------
#define BATCH 2048
#define NC    4
#define NRIS  100
#define DIN   303
#define D1    1024
#define D2    1024
#define D3    512
#define DOUT  264
#define INV_THRESH 1.0e15f

#define KP1 320
#define KP2 1024
#define KP3 1024
#define KP4 512

// ---------------- scratch ----------------
__device__ float g_h1[BATCH * D1];
__device__ float g_h2[BATCH * D2];
__device__ float g_h3[BATCH * D3];
__device__ float g_t1[BATCH * DOUT];
__device__ float g_thetaN[BATCH * 2 * NRIS];
__device__ float g_ccc[BATCH * NC];

__device__ __nv_bfloat16 g_W1h[D1 * KP1], g_W1l[D1 * KP1];
__device__ __nv_bfloat16 g_W2h[D2 * KP2], g_W2l[D2 * KP2];
__device__ __nv_bfloat16 g_W3h[D3 * KP3], g_W3l[D3 * KP3];
__device__ __nv_bfloat16 g_W4h[DOUT * KP4], g_W4l[DOUT * KP4];

// ---------------- low-level helpers ----------------
__device__ __forceinline__ uint32_t s2u(const void* p) {
    uint32_t a;
    asm("{ .reg .u64 t; cvta.to.shared.u64 t, %1; cvt.u32.u64 %0, t; }"
        : "=r"(a) : "l"(p));
    return a;
}
__device__ __forceinline__ void ldsm_x4(uint32_t* r, uint32_t addr) {
    asm volatile("ldmatrix.sync.aligned.m8n8.x4.shared.b16 {%0,%1,%2,%3}, [%4];"
                 : "=r"(r[0]), "=r"(r[1]), "=r"(r[2]), "=r"(r[3]) : "r"(addr));
}
__device__ __forceinline__ void mma16816(float* d, const uint32_t* a,
                                         const uint32_t* b) {
    asm volatile(
        "mma.sync.aligned.m16n8k16.row.col.f32.bf16.bf16.f32 "
        "{%0,%1,%2,%3}, {%4,%5,%6,%7}, {%8,%9}, {%0,%1,%2,%3};"
        : "+f"(d[0]), "+f"(d[1]), "+f"(d[2]), "+f"(d[3])
        : "r"(a[0]), "r"(a[1]), "r"(a[2]), "r"(a[3]), "r"(b[0]), "r"(b[1]));
}
__device__ __forceinline__ void cp16(uint32_t dst, const void* src, bool pred) {
    int sz = pred ? 16 : 0;
    asm volatile("cp.async.cg.shared.global [%0], [%1], 16, %2;"
                 :: "r"(dst), "l"(src), "r"(sz));
}
#define CP_COMMIT() asm volatile("cp.async.commit_group;" ::: "memory")
#define CP_WAIT(n)  asm volatile("cp.async.wait_group %0;" :: "n"(n) : "memory")

__device__ __forceinline__ uint32_t pack_bf16(float lo, float hi) {
    uint32_t r;
    asm("cvt.rn.bf16x2.f32 %0, %1, %2;" : "=r"(r) : "f"(hi), "f"(lo));
    return r;
}
#define SWZ(b) ((b) ^ (((b) >> 3) & 0x70))

// ---------------- fused weight transpose + bf16 split -----------------------
#define NBX1 (KP1 / 32)
#define NBX2 (KP2 / 32)
#define NBX3 (KP3 / 32)
#define NBX4 (KP4 / 32)
#define NB1 (NBX1 * ((D1 + 31) / 32))
#define NB2 (NBX2 * ((D2 + 31) / 32))
#define NB3 (NBX3 * ((D3 + 31) / 32))
#define NB4 (NBX4 * ((DOUT + 31) / 32))
#define NB_TOTAL (NB1 + NB2 + NB3 + NB4)

__global__ __launch_bounds__(256) void split_transpose_all(
    const float* __restrict__ W1a, const float* __restrict__ W2a,
    const float* __restrict__ W3a, const float* __restrict__ W4a,
    __nv_bfloat16* __restrict__ h1, __nv_bfloat16* __restrict__ l1,
    __nv_bfloat16* __restrict__ h2, __nv_bfloat16* __restrict__ l2,
    __nv_bfloat16* __restrict__ h3, __nv_bfloat16* __restrict__ l3,
    __nv_bfloat16* __restrict__ h4, __nv_bfloat16* __restrict__ l4)
{
    int bid = blockIdx.x;
    const float* W; __nv_bfloat16 *Wh, *Wl;
    int K, N, Kp, nbx, r;
    if (bid < NB1) {
        W = W1a; Wh = h1; Wl = l1; K = DIN; N = D1; Kp = KP1; nbx = NBX1; r = bid;
    } else if (bid < NB1 + NB2) {
        W = W2a; Wh = h2; Wl = l2; K = D1; N = D2; Kp = KP2; nbx = NBX2; r = bid - NB1;
    } else if (bid < NB1 + NB2 + NB3) {
        W = W3a; Wh = h3; Wl = l3; K = D2; N = D3; Kp = KP3; nbx = NBX3; r = bid - NB1 - NB2;
    } else {
        W = W4a; Wh = h4; Wl = l4; K = D3; N = DOUT; Kp = KP4; nbx = NBX4; r = bid - NB1 - NB2 - NB3;
    }
    int k0 = (r % nbx) * 32, n0 = (r / nbx) * 32;

    __shared__ float tile[32][33];
    int tx = threadIdx.x % 32, ty = threadIdx.x / 32;
#pragma unroll
    for (int i = 0; i < 4; i++) {
        int k = k0 + ty + i * 8, n = n0 + tx;
        tile[ty + i * 8][tx] = (k < K && n < N) ? W[(size_t)k * N + n] : 0.f;
    }
    __syncthreads();
#pragma unroll
    for (int i = 0; i < 4; i++) {
        int n = n0 + ty + i * 8, k = k0 + tx;
        if (n < N) {
            float v = tile[tx][ty + i * 8];
            __nv_bfloat16 h = __float2bfloat16(v);
            float rr = v - __bfloat162float(h);
            Wh[(size_t)n * Kp + k] = h;
            Wl[(size_t)n * Kp + k] = __float2bfloat16(rr);
        }
    }
}

// ---------------- mma.sync bf16-split GEMM ----------------------------------
// C[M,N] = relu?(A[M,K]fp32 @ W^T + bias). BM=64, BN=128.
// 8 warps: 2 along M x 4 along N, warp tile 32x32.
// 3-pass split: AhBh + AlBh + AhBl. Double-buffered, 2 CTAs/SM.
#define ABYTES 8192                       // one A buffer (64 rows x 128B)
#define STAGE  (2 * ABYTES + 32768)       // Ah, Al, Bh(16K), Bl(16K)
#define SMEM_GEMM (2 * STAGE)             // 98304

__global__ __launch_bounds__(256, 2) void gemm_mma(
    const float* __restrict__ A,
    const __nv_bfloat16* __restrict__ Wh,
    const __nv_bfloat16* __restrict__ Wl,
    const float* __restrict__ bias, float* __restrict__ C,
    int M, int N, int K, int Kp, int relu, int kaligned)
{
    constexpr int NT = 4;              // 8-col tiles per warp (32 cols)

    extern __shared__ char smem[];
    const uint32_t sb = s2u(smem);
    const int tid  = threadIdx.x;
    const int lane = tid & 31;
    const int wid  = tid >> 5;
    const int wm   = wid & 1;          // 0..1 -> 32*wm
    const int wn   = wid >> 1;         // 0..3 -> 32*wn
    const int m0 = blockIdx.y * 64;
    const int n0 = blockIdx.x * 128;
    const int nch = Kp >> 6;

    float acc[2][NT][4];
#pragma unroll
    for (int mt = 0; mt < 2; mt++)
#pragma unroll
        for (int nt = 0; nt < NT; nt++)
#pragma unroll
            for (int e = 0; e < 4; e++) acc[mt][nt][e] = 0.f;

    float av[2][8];

    auto ldgA = [&](int c) {
        const int kk0 = c * 64;
#pragma unroll
        for (int g = 0; g < 2; g++) {
            int t = tid + g * 256;
            int m = t >> 3, j = t & 7;
            const float* ap = A + (size_t)(m0 + m) * K + kk0 + j * 8;
            if (kaligned) {
                float4 p0 = *(const float4*)ap;
                float4 p1 = *(const float4*)(ap + 4);
                av[g][0] = p0.x; av[g][1] = p0.y; av[g][2] = p0.z; av[g][3] = p0.w;
                av[g][4] = p1.x; av[g][5] = p1.y; av[g][6] = p1.z; av[g][7] = p1.w;
            } else {
#pragma unroll
                for (int e = 0; e < 8; e++)
                    av[g][e] = (kk0 + j * 8 + e < K) ? ap[e] : 0.f;
            }
        }
    };
    auto stsA = [&](int c) {
        const uint32_t s = (uint32_t)(c & 1) * STAGE;
#pragma unroll
        for (int g = 0; g < 2; g++) {
            int t = tid + g * 256;
            int m = t >> 3, j = t & 7;
            uint32_t hp[4], lp[4];
#pragma unroll
            for (int q = 0; q < 4; q++) {
                float v0 = av[g][2 * q], v1 = av[g][2 * q + 1];
                __nv_bfloat16 h0 = __float2bfloat16(v0);
                __nv_bfloat16 h1 = __float2bfloat16(v1);
                float r0 = v0 - __bfloat162float(h0);
                float r1 = v1 - __bfloat162float(h1);
                hp[q] = (uint32_t)__bfloat16_as_ushort(h0) |
                        ((uint32_t)__bfloat16_as_ushort(h1) << 16);
                lp[q] = pack_bf16(__bfloat162float(__float2bfloat16(r0)),
                                  __bfloat162float(__float2bfloat16(r1)));
            }
            uint32_t sw = SWZ((uint32_t)(m * 128 + j * 16));
            *(uint4*)(smem + s + sw)          = make_uint4(hp[0], hp[1], hp[2], hp[3]);
            *(uint4*)(smem + s + ABYTES + sw) = make_uint4(lp[0], lp[1], lp[2], lp[3]);
        }
    };
    auto stageB = [&](int c) {
        const uint32_t s = (uint32_t)(c & 1) * STAGE;
        const int kk0 = c * 64;
#pragma unroll
        for (int g = 0; g < 4; g++) {
            int t = tid + g * 256;
            int n = t >> 3, j = t & 7;
            bool ok = (n0 + n) < N;
            int row = ok ? (n0 + n) : 0;
            uint32_t sw = SWZ((uint32_t)(n * 128 + j * 16));
            cp16(sb + s + 2 * ABYTES + sw,         Wh + (size_t)row * Kp + kk0 + j * 8, ok);
            cp16(sb + s + 2 * ABYTES + 16384 + sw, Wl + (size_t)row * Kp + kk0 + j * 8, ok);
        }
    };

    const int qa = lane >> 3;
    const uint32_t rowA  = (uint32_t)(wm * 32 + (qa & 1) * 8 + (lane & 7));
    const uint32_t kaOff = (uint32_t)((qa >> 1) * 16);
    // paired-B ldmatrix.x4 lane map: 2 n-tiles x 2 k-halves
    const uint32_t rowBp = (uint32_t)(wn * 32 + ((lane >> 4) & 1) * 8 + (lane & 7));
    const uint32_t kbOff = (uint32_t)(((lane >> 3) & 1) * 16);

    auto compute = [&](int c) {
        const uint32_t s = (uint32_t)(c & 1) * STAGE;
        const uint32_t bAh = sb + s, bAl = sb + s + ABYTES;
        const uint32_t bBh = sb + s + 2 * ABYTES, bBl = bBh + 16384;
#pragma unroll
        for (int s16 = 0; s16 < 4; s16++) {
            uint32_t a_h[2][4], a_l[2][4];
#pragma unroll
            for (int mt = 0; mt < 2; mt++) {
                uint32_t off = SWZ((rowA + mt * 16) * 128 + s16 * 32 + kaOff);
                ldsm_x4(a_h[mt], bAh + off);
                ldsm_x4(a_l[mt], bAl + off);
            }
            uint32_t b_h[NT][2], b_l[NT][2];
#pragma unroll
            for (int ntp = 0; ntp < NT / 2; ntp++) {
                uint32_t off = SWZ((rowBp + ntp * 16) * 128 + s16 * 32 + kbOff);
                uint32_t r4[4];
                ldsm_x4(r4, bBh + off);
                b_h[2 * ntp][0] = r4[0]; b_h[2 * ntp][1] = r4[1];
                b_h[2 * ntp + 1][0] = r4[2]; b_h[2 * ntp + 1][1] = r4[3];
                ldsm_x4(r4, bBl + off);
                b_l[2 * ntp][0] = r4[0]; b_l[2 * ntp][1] = r4[1];
                b_l[2 * ntp + 1][0] = r4[2]; b_l[2 * ntp + 1][1] = r4[3];
            }
#pragma unroll
            for (int mt = 0; mt < 2; mt++)
#pragma unroll
                for (int nt = 0; nt < NT; nt++) {
                    mma16816(acc[mt][nt], a_h[mt], b_h[nt]);
                    mma16816(acc[mt][nt], a_l[mt], b_h[nt]);
                    mma16816(acc[mt][nt], a_h[mt], b_l[nt]);
                }
        }
    };

    stageB(0); CP_COMMIT();
    ldgA(0);
    stsA(0);

    for (int c = 0; c < nch; c++) {
        if (c + 1 < nch) {
            ldgA(c + 1);
            stageB(c + 1); CP_COMMIT();
            CP_WAIT(1);
        } else {
            CP_WAIT(0);
        }
        __syncthreads();
        compute(c);
        if (c + 1 < nch) stsA(c + 1);
        __syncthreads();
    }

#pragma unroll
    for (int mt = 0; mt < 2; mt++) {
        int r0 = m0 + wm * 32 + mt * 16 + (lane >> 2);
#pragma unroll
        for (int nt = 0; nt < NT; nt++) {
            int col = n0 + wn * 32 + nt * 8 + (lane & 3) * 2;
            if (col >= N) continue;
            float2 bv = *(const float2*)(bias + col);
            float o0 = acc[mt][nt][0] + bv.x;
            float o1 = acc[mt][nt][1] + bv.y;
            float o2 = acc[mt][nt][2] + bv.x;
            float o3 = acc[mt][nt][3] + bv.y;
            if (relu) {
                o0 = fmaxf(o0, 0.f); o1 = fmaxf(o1, 0.f);
                o2 = fmaxf(o2, 0.f); o3 = fmaxf(o3, 0.f);
            }
            *(float2*)(C + (size_t)r0 * N + col)       = make_float2(o0, o1);
            *(float2*)(C + (size_t)(r0 + 8) * N + col) = make_float2(o2, o3);
        }
    }
}

// ---------------- postprocess: unit-modulus theta + precoder normalization --
__global__ __launch_bounds__(128) void postproc_kernel(
    const float* __restrict__ t1, float* __restrict__ thetaN,
    float* __restrict__ out)
{
    const int b   = blockIdx.x;
    const int tid = threadIdx.x;
    const float* row  = t1  + (size_t)b * DOUT;
    float*       orow = out + (size_t)b * DOUT;

    __shared__ float s[2];

    if (tid < NRIS) {
        float re = row[tid];
        float im = row[NRIS + tid];
        float inv = rsqrtf(re * re + im * im);
        thetaN[(size_t)b * 200 + tid]       = re * inv;
        thetaN[(size_t)b * 200 + 100 + tid] = im * inv;
    }

    int w = tid >> 5, l = tid & 31;
    if (w < 2) {
        int base = 200 + 32 * w;
        float v = 0.f;
        if (l < 16) {
            float re = row[base + l];
            float im = row[base + 16 + l];
            v = re * re + im * im;
        }
#pragma unroll
        for (int o = 8; o; o >>= 1) v += __shfl_down_sync(0xffffffffu, v, o);
        if (l == 0) s[w] = sqrtf(2.0f / v);
    }
    __syncthreads();

    if (tid < 64) {
        int col  = 200 + tid;
        float sc = (tid < 32) ? s[0] : s[1];
        orow[col] = row[col] * sc;
    }
}

// ---------------- quad pass 1: CCC[b][c] = Re(theta^H T_c theta)/thr --------
__global__ __launch_bounds__(256) void quad_pass1(
    const float* __restrict__ Tr, const float* __restrict__ Ti,
    const float* __restrict__ thetaN, float* __restrict__ ccc)
{
    const int bc = blockIdx.x;
    const int b  = bc >> 2;
    const int tid = threadIdx.x;

    __shared__ float sa[100], sb_[100];
    __shared__ float da[4][32], db[4][32];   // da[e][q] = sa[4q+e]
    __shared__ float wsum[8];

    if (tid < 200) {
        float v = thetaN[(size_t)b * 200 + tid];
        if (tid < 100) {
            sa[tid] = v;
            da[tid & 3][tid >> 2] = v;
        } else {
            int t = tid - 100;
            sb_[t] = v;
            db[t & 3][t >> 2] = v;
        }
    }
    __syncthreads();

    const float4* TrV = (const float4*)(Tr + (size_t)bc * 10000);
    const float4* TiV = (const float4*)(Ti + (size_t)bc * 10000);

    float acc = 0.f;
    for (int i = tid; i < 2500; i += 256) {
        int n = i / 25;
        int q = i - n * 25;
        float4 tr = __ldcs(TrV + i);
        float4 ti = __ldcs(TiV + i);
        float an = sa[n], bn = sb_[n];
        {
            float am = da[0][q], bm = db[0][q];
            acc += tr.x * (an * am + bn * bm) + ti.x * (bn * am - an * bm);
        }
        {
            float am = da[1][q], bm = db[1][q];
            acc += tr.y * (an * am + bn * bm) + ti.y * (bn * am - an * bm);
        }
        {
            float am = da[2][q], bm = db[2][q];
            acc += tr.z * (an * am + bn * bm) + ti.z * (bn * am - an * bm);
        }
        {
            float am = da[3][q], bm = db[3][q];
            acc += tr.w * (an * am + bn * bm) + ti.w * (bn * am - an * bm);
        }
    }

#pragma unroll
    for (int o = 16; o; o >>= 1) acc += __shfl_down_sync(0xffffffffu, acc, o);
    if ((tid & 31) == 0) wsum[tid >> 5] = acc;
    __syncthreads();
    if (tid == 0) {
        float s = 0.f;
#pragma unroll
        for (int w = 0; w < 8; w++) s += wsum[w];
        ccc[bc] = s * INV_THRESH;
    }
}

// ---------------- quad pass 2: scale + write theta_hat ----------------------
__global__ __launch_bounds__(256) void quad_pass2(
    const float* __restrict__ ccc, const float* __restrict__ thetaN,
    float* __restrict__ out)
{
    const int b = blockIdx.x;
    const int tid = threadIdx.x;
    float c0 = ccc[b * 4 + 0], c1 = ccc[b * 4 + 1];
    float c2 = ccc[b * 4 + 2], c3 = ccc[b * 4 + 3];
    float mx = fmaxf(fmaxf(c0, c1), fmaxf(c2, c3));
    float scale = rsqrtf(fmaxf(mx, 1.0f));
    if (tid < 200)
        out[(size_t)b * DOUT + tid] = thetaN[(size_t)b * 200 + tid] * scale;
}

// ---------------- launch ----------------------------------------------------
extern "C" void kernel_launch(void* const* d_in, const int* in_sizes, int n_in,
                              void* d_out, int out_size)
{
    const float* X  = (const float*)d_in[0];
    const float* Tr = (const float*)d_in[1];
    const float* Ti = (const float*)d_in[2];
    const float* W1 = (const float*)d_in[3];
    const float* b1 = (const float*)d_in[4];
    const float* W2 = (const float*)d_in[5];
    const float* b2 = (const float*)d_in[6];
    const float* W3 = (const float*)d_in[7];
    const float* b3 = (const float*)d_in[8];
    const float* W4 = (const float*)d_in[9];
    const float* b4 = (const float*)d_in[10];
    float* out = (float*)d_out;

    float *h1, *h2, *h3, *t1, *thN, *ccc;
    cudaGetSymbolAddress((void**)&h1,  g_h1);
    cudaGetSymbolAddress((void**)&h2,  g_h2);
    cudaGetSymbolAddress((void**)&h3,  g_h3);
    cudaGetSymbolAddress((void**)&t1,  g_t1);
    cudaGetSymbolAddress((void**)&thN, g_thetaN);
    cudaGetSymbolAddress((void**)&ccc, g_ccc);

    __nv_bfloat16 *w1h, *w1l, *w2h, *w2l, *w3h, *w3l, *w4h, *w4l;
    cudaGetSymbolAddress((void**)&w1h, g_W1h);
    cudaGetSymbolAddress((void**)&w1l, g_W1l);
    cudaGetSymbolAddress((void**)&w2h, g_W2h);
    cudaGetSymbolAddress((void**)&w2l, g_W2l);
    cudaGetSymbolAddress((void**)&w3h, g_W3h);
    cudaGetSymbolAddress((void**)&w3l, g_W3l);
    cudaGetSymbolAddress((void**)&w4h, g_W4h);
    cudaGetSymbolAddress((void**)&w4l, g_W4l);

    cudaFuncSetAttribute(gemm_mma, cudaFuncAttributeMaxDynamicSharedMemorySize,
                         SMEM_GEMM);

    split_transpose_all<<<NB_TOTAL, 256>>>(W1, W2, W3, W4,
                                           w1h, w1l, w2h, w2l,
                                           w3h, w3l, w4h, w4l);

    gemm_mma<<<dim3(D1 / 128, BATCH / 64), 256, SMEM_GEMM>>>(
        X, w1h, w1l, b1, h1, BATCH, D1, DIN, KP1, 1, 0);
    gemm_mma<<<dim3(D2 / 128, BATCH / 64), 256, SMEM_GEMM>>>(
        h1, w2h, w2l, b2, h2, BATCH, D2, D1, KP2, 1, 1);
    gemm_mma<<<dim3(D3 / 128, BATCH / 64), 256, SMEM_GEMM>>>(
        h2, w3h, w3l, b3, h3, BATCH, D3, D2, KP3, 1, 1);
    gemm_mma<<<dim3((DOUT + 127) / 128, BATCH / 64), 256, SMEM_GEMM>>>(
        h3, w4h, w4l, b4, t1, BATCH, DOUT, D3, KP4, 0, 1);

    postproc_kernel<<<BATCH, 128>>>(t1, thN, out);
    quad_pass1<<<BATCH * NC, 256>>>(Tr, Ti, thN, ccc);
    quad_pass2<<<BATCH, 256>>>(ccc, thN, out);
}